// round 11
// baseline (speedup 1.0000x reference)
#include <cuda_runtime.h>
#include <cuda_fp16.h>
#include <cstdint>

// ---------------------------------------------------------------------------
// Problem constants
// ---------------------------------------------------------------------------
#define P_ATOMS 512
#define A_CH    4
#define K_DIM   49
#define N_DIM   8
#define NM      128
#define NM2     (NM*NM)
#define NM3     (NM*NM*NM)
#define NB      64              // blocks per dim (Morton-2)
#define G_PTS   1900
#define G_PAD   1920
#define G_SORT  2048            // bitonic size
#define M_ROWS  (P_ATOMS*A_CH)  // 2048
#define KN_COLS (K_DIM*N_DIM)   // 392
#define KN_PAD  512             // 4 * 128

#define KSPLIT  4
#define KCHUNK  480             // 4*480 = 1920
#define BM      128
#define BN      128
#define BK      32
#define NIT     (KCHUNK/BK)     // 15
#define BKPH    (BK + 8)        // padded row stride in halves (40 -> 80 B rows)
#define NSTAGES 4

#define A_STAGE_H (BM * BKPH)           // 5120 halves
#define B_STAGE_H (BN * BKPH)           // 5120 halves
#define SMEM_BYTES (NSTAGES * (A_STAGE_H + B_STAGE_H) * 2)   // 81920 B

// ---------------------------------------------------------------------------
// Device scratch (zero-initialized at module load; pads never written)
// ---------------------------------------------------------------------------
__device__ __half g_Fh[M_ROWS * G_PAD];              // 7.9 MB
__device__ __half g_V2h[KN_PAD * G_PAD];             // 2.0 MB
__device__ __align__(128) uint2 g_meshT[NM3];        // 16.8 MB  fp16x4, Morton-2
__device__ float  g_w2[G_PTS];
__device__ float4 g_grid2[G_PTS];
__device__ float  g_inv[9];
__device__ uint32_t g_perm[G_SORT];                  // g2 -> original g

// ---------------------------------------------------------------------------
// helpers
// ---------------------------------------------------------------------------
#define CP_ASYNC16(dst, src) \
    asm volatile("cp.async.cg.shared.global [%0], [%1], 16;" :: "r"(dst), "l"(src) : "memory")
#define CP_COMMIT() asm volatile("cp.async.commit_group;" ::: "memory")
#define CP_WAIT(n)  asm volatile("cp.async.wait_group %0;" :: "n"(n) : "memory")

#define MMA_F16(c, a, b) \
    asm volatile("mma.sync.aligned.m16n8k16.row.col.f32.f16.f16.f32 " \
        "{%0,%1,%2,%3}, {%4,%5,%6,%7}, {%8,%9}, {%0,%1,%2,%3};" \
        : "+f"((c)[0]), "+f"((c)[1]), "+f"((c)[2]), "+f"((c)[3]) \
        : "r"((a)[0]), "r"((a)[1]), "r"((a)[2]), "r"((a)[3]), \
          "r"((b)[0]), "r"((b)[1]))

#define LDSM_X4(r0, r1, r2, r3, addr) \
    asm volatile("ldmatrix.sync.aligned.m8n8.x4.shared.b16 {%0,%1,%2,%3}, [%4];" \
        : "=r"(r0), "=r"(r1), "=r"(r2), "=r"(r3) : "r"(addr))

__device__ __forceinline__ uint32_t pack_h2(float a, float b) {
    __half2 h = __floats2half2_rn(a, b);
    return *reinterpret_cast<uint32_t*>(&h);
}

__device__ __forceinline__ uint32_t expand_bits3(uint32_t x) {
    x &= 0x3FF;
    x = (x | (x << 16)) & 0x030000FF;
    x = (x | (x << 8))  & 0x0300F00F;
    x = (x | (x << 4))  & 0x030C30C3;
    x = (x | (x << 2))  & 0x09249249;
    return x;
}

// ---------------------------------------------------------------------------
// Kernel 0: sort grid points by Morton code of their cell-block coordinate.
// Single block, 1024 threads, bitonic sort of 2048 packed (key|idx) words.
// Also computes the cell inverse (needed for the keys and later kernels).
// ---------------------------------------------------------------------------
__global__ void __launch_bounds__(1024)
sort_kernel(const float* __restrict__ grid, const float* __restrict__ cell) {
    __shared__ uint32_t s[G_SORT];
    int tid = threadIdx.x;

    // thread 0 computes inverse; all threads need it -> broadcast via smem
    __shared__ float sinv[9];
    if (tid == 0) {
        float c00 = cell[0], c01 = cell[1], c02 = cell[2];
        float c10 = cell[3], c11 = cell[4], c12 = cell[5];
        float c20 = cell[6], c21 = cell[7], c22 = cell[8];
        float m00 = c11*c22 - c12*c21;
        float m01 = c02*c21 - c01*c22;
        float m02 = c01*c12 - c02*c11;
        float m10 = c12*c20 - c10*c22;
        float m11 = c00*c22 - c02*c20;
        float m12 = c02*c10 - c00*c12;
        float m20 = c10*c21 - c11*c20;
        float m21 = c01*c20 - c00*c21;
        float m22 = c00*c11 - c01*c10;
        float rdet = 1.0f / (c00*m00 + c01*m10 + c02*m20);
        sinv[0] = m00*rdet; sinv[1] = m01*rdet; sinv[2] = m02*rdet;
        sinv[3] = m10*rdet; sinv[4] = m11*rdet; sinv[5] = m12*rdet;
        sinv[6] = m20*rdet; sinv[7] = m21*rdet; sinv[8] = m22*rdet;
        g_inv[0]=sinv[0]; g_inv[1]=sinv[1]; g_inv[2]=sinv[2];
        g_inv[3]=sinv[3]; g_inv[4]=sinv[4]; g_inv[5]=sinv[5];
        g_inv[6]=sinv[6]; g_inv[7]=sinv[7]; g_inv[8]=sinv[8];
    }
    __syncthreads();

    // build keys
    for (int i = tid; i < G_SORT; i += 1024) {
        uint32_t key;
        if (i < G_PTS) {
            float gx = __ldg(grid + i*3 + 0);
            float gy = __ldg(grid + i*3 + 1);
            float gz = __ldg(grid + i*3 + 2);
            float ux = (gx*sinv[0] + gy*sinv[3] + gz*sinv[6]) * (float)NM;
            float uy = (gx*sinv[1] + gy*sinv[4] + gz*sinv[7]) * (float)NM;
            float uz = (gx*sinv[2] + gy*sinv[5] + gz*sinv[8]) * (float)NM;
            // offsets span ~[-64,64] cells; shift positive, block coords (>>1)
            uint32_t bx = ((uint32_t)(int)(floorf(ux) + 128.f)) >> 1;  // 7 bits
            uint32_t by = ((uint32_t)(int)(floorf(uy) + 128.f)) >> 1;
            uint32_t bz = ((uint32_t)(int)(floorf(uz) + 128.f)) >> 1;
            uint32_t m = expand_bits3(bx) | (expand_bits3(by) << 1) | (expand_bits3(bz) << 2);
            key = (m << 11) | (uint32_t)i;
        } else {
            key = 0xFFFFFFFFu;
        }
        s[i] = key;
    }
    __syncthreads();

    // bitonic sort, 1024 threads, one compare-exchange pair per thread per step
    for (int k = 2; k <= G_SORT; k <<= 1) {
        for (int j = k >> 1; j > 0; j >>= 1) {
            int t = tid;
            int i = ((t & ~(j - 1)) << 1) | (t & (j - 1));
            int p = i | j;
            bool up = ((i & k) == 0);
            uint32_t a = s[i], b = s[p];
            if ((a > b) == up) { s[i] = b; s[p] = a; }
            __syncthreads();
        }
    }

    for (int i = tid; i < G_SORT; i += 1024)
        g_perm[i] = s[i] & 0x7FFu;
}

// ---------------------------------------------------------------------------
// Kernel A: prep (Morton block transpose -> fp16, V2/weights/grid permute)
// ---------------------------------------------------------------------------
__global__ void __launch_bounds__(256)
prep_kernel(const float* __restrict__ mesh,
            const float* __restrict__ values,
            const float* __restrict__ weights,
            const float* __restrict__ grid) {
    int i = blockIdx.x * blockDim.x + threadIdx.x;
    if (i < NB*NB*NB) {
        int bz = i & 63, by = (i >> 6) & 63, bx = i >> 12;
        uint2 cells[8];
        #pragma unroll
        for (int jx = 0; jx < 2; ++jx) {
            #pragma unroll
            for (int jy = 0; jy < 2; ++jy) {
                int x = 2*bx + jx, y = 2*by + jy;
                const float* base = mesh + ((size_t)x * NM + y) * NM + 2*bz;
                float2 f0 = __ldg((const float2*)(base));
                float2 f1 = __ldg((const float2*)(base + NM3));
                float2 f2 = __ldg((const float2*)(base + 2*NM3));
                float2 f3 = __ldg((const float2*)(base + 3*NM3));
                int o = jx*4 + jy*2;
                cells[o    ] = make_uint2(pack_h2(f0.x, f1.x), pack_h2(f2.x, f3.x));
                cells[o + 1] = make_uint2(pack_h2(f0.y, f1.y), pack_h2(f2.y, f3.y));
            }
        }
        uint4* dst = reinterpret_cast<uint4*>(g_meshT + (size_t)i * 8);
        const uint4* src = reinterpret_cast<const uint4*>(cells);
        dst[0] = src[0]; dst[1] = src[1]; dst[2] = src[2]; dst[3] = src[3];
    }
    if (i < KN_COLS * G_PTS) {
        int row = i / G_PTS;
        int g2  = i - row * G_PTS;
        int g   = (int)g_perm[g2];
        g_V2h[row * G_PAD + g2] = __float2half_rn(__ldg(values + row * G_PTS + g));
    }
    if (i < G_PTS) {
        int g = (int)g_perm[i];
        g_w2[i] = __ldg(weights + g);
        float4 gp;
        gp.x = __ldg(grid + g*3 + 0);
        gp.y = __ldg(grid + g*3 + 1);
        gp.z = __ldg(grid + g*3 + 2);
        gp.w = 0.f;
        g_grid2[i] = gp;
    }
}

// ---------------------------------------------------------------------------
// Kernel B: B-spline interpolation -> fp16 F[(p,a)][g2]
// 18 LDG.128 batched (MLP=18); warp lanes are Morton-adjacent grid points.
// ---------------------------------------------------------------------------
__global__ void __launch_bounds__(256)
interp_kernel(const float* __restrict__ pos) {
    int tid = blockIdx.x * blockDim.x + threadIdx.x;
    if (tid >= P_ATOMS * G_PTS) return;
    int p  = tid / G_PTS;
    int g2 = tid - p * G_PTS;

    float m00 = g_inv[0], m01 = g_inv[1], m02 = g_inv[2];
    float m10 = g_inv[3], m11 = g_inv[4], m12 = g_inv[5];
    float m20 = g_inv[6], m21 = g_inv[7], m22 = g_inv[8];

    float4 gp = g_grid2[g2];
    float px = __ldg(pos + p*3 + 0) + gp.x;
    float py = __ldg(pos + p*3 + 1) + gp.y;
    float pz = __ldg(pos + p*3 + 2) + gp.z;

    float fx = px*m00 + py*m10 + pz*m20;
    float fy = px*m01 + py*m11 + pz*m21;
    float fz = px*m02 + py*m12 + pz*m22;

    float wx[3], wy[3];
    int xpart[3], ypart[3];
    {
        float u = fx * (float)NM, nf = floorf(u + 0.5f), x = u - nf;
        wx[0] = 0.5f*(0.5f-x)*(0.5f-x); wx[1] = 0.75f - x*x; wx[2] = 0.5f*(0.5f+x)*(0.5f+x);
        int n = (int)nf;
        #pragma unroll
        for (int d = 0; d < 3; ++d) {
            int v = (n + d - 1 + 4*NM) & (NM-1);
            xpart[d] = (v >> 1) * 16384 + (v & 1) * 2;
        }
    }
    {
        float u = fy * (float)NM, nf = floorf(u + 0.5f), x = u - nf;
        wy[0] = 0.5f*(0.5f-x)*(0.5f-x); wy[1] = 0.75f - x*x; wy[2] = 0.5f*(0.5f+x)*(0.5f+x);
        int n = (int)nf;
        #pragma unroll
        for (int d = 0; d < 3; ++d) {
            int v = (n + d - 1 + 4*NM) & (NM-1);
            ypart[d] = (v >> 1) * 256 + (v & 1);
        }
    }
    int zpart[2];
    float zwA[2], zwB[2];
    {
        float u = fz * (float)NM, nf = floorf(u + 0.5f), x = u - nf;
        float wz0 = 0.5f*(0.5f-x)*(0.5f-x);
        float wz1 = 0.75f - x*x;
        float wz2 = 0.5f*(0.5f+x)*(0.5f+x);
        int nn = (int)nf + 4*NM;
        int b_lo = ((nn - 1) & (NM-1)) >> 1;
        int b_hi = ((nn + 1) & (NM-1)) >> 1;
        zpart[0] = b_lo * 4;
        zpart[1] = b_hi * 4;
        bool odd = (nn & 1) != 0;
        zwA[0] = odd ? wz0 : 0.f;
        zwB[0] = odd ? wz1 : wz0;
        zwA[1] = odd ? wz2 : wz1;
        zwB[1] = odd ? 0.f : wz2;
    }

    const uint4* mesh4 = reinterpret_cast<const uint4*>(g_meshT);

    uint4 v[18];
    #pragma unroll
    for (int dx = 0; dx < 3; ++dx)
        #pragma unroll
        for (int dy = 0; dy < 3; ++dy)
            #pragma unroll
            for (int dz = 0; dz < 2; ++dz)
                v[(dx*3 + dy)*2 + dz] = __ldg(mesh4 + xpart[dx] + ypart[dy] + zpart[dz]);

    float acc0 = 0.f, acc1 = 0.f, acc2 = 0.f, acc3 = 0.f;
    #pragma unroll
    for (int dx = 0; dx < 3; ++dx) {
        #pragma unroll
        for (int dy = 0; dy < 3; ++dy) {
            float wxy = wx[dx] * wy[dy];
            #pragma unroll
            for (int dz = 0; dz < 2; ++dz) {
                uint4 q = v[(dx*3 + dy)*2 + dz];
                float wA = wxy * zwA[dz];
                float wB = wxy * zwB[dz];
                float2 a01 = __half22float2(*reinterpret_cast<__half2*>(&q.x));
                float2 a23 = __half22float2(*reinterpret_cast<__half2*>(&q.y));
                float2 b01 = __half22float2(*reinterpret_cast<__half2*>(&q.z));
                float2 b23 = __half22float2(*reinterpret_cast<__half2*>(&q.w));
                acc0 += wA * a01.x + wB * b01.x;
                acc1 += wA * a01.y + wB * b01.y;
                acc2 += wA * a23.x + wB * b23.x;
                acc3 += wA * a23.y + wB * b23.y;
            }
        }
    }

    float wt = g_w2[g2];
    g_Fh[(p*A_CH + 0)*G_PAD + g2] = __float2half_rn(acc0 * wt);
    g_Fh[(p*A_CH + 1)*G_PAD + g2] = __float2half_rn(acc1 * wt);
    g_Fh[(p*A_CH + 2)*G_PAD + g2] = __float2half_rn(acc2 * wt);
    g_Fh[(p*A_CH + 3)*G_PAD + g2] = __float2half_rn(acc3 * wt);
}

// ---------------------------------------------------------------------------
// Kernel C: fp16 mma.sync GEMM with ldmatrix, 4-stage cp.async, split-K 4.
// Block 128x128, BK=32, 8 warps (warp tile 64x32). atomicAdd epilogue.
// ---------------------------------------------------------------------------
__global__ void __launch_bounds__(256, 1)
gemm_mma_kernel(float* __restrict__ out) {
    extern __shared__ __half smemh[];
    __half* As = smemh;                          // [4][BM][BKPH]
    __half* Bs = smemh + NSTAGES * A_STAGE_H;    // [4][BN][BKPH]

    const int tid  = threadIdx.x;
    const int lane = tid & 31;
    const int wid  = tid >> 5;
    const int warpM = wid & 1;
    const int warpN = wid >> 1;
    const int gRow = lane >> 2;
    const int gCol = lane & 3;

    const int n0    = blockIdx.x * BN;
    const int m0    = blockIdx.y * BM;
    const int bz    = blockIdx.z;
    const int kbase = bz * KCHUNK;

    uint32_t asBase = (uint32_t)__cvta_generic_to_shared(As);
    uint32_t bsBase = (uint32_t)__cvta_generic_to_shared(Bs);

    const int rowA_l = (lane & 7) + (((lane >> 3) & 1) << 3);
    const int kA_l   = (lane >> 4) << 3;
    const int rowB_l = (lane & 7) + ((lane >> 4) << 3);
    const int kB_l   = ((lane >> 3) & 1) << 3;

    auto load_stage = [&](int it, int buf) {
        int kofs = kbase + it * BK;
        #pragma unroll
        for (int i = 0; i < 2; ++i) {
            int e   = tid + i * 256;
            int row = e >> 2;
            int c8  = e & 3;
            uint32_t dstA = asBase + (buf * A_STAGE_H + row * BKPH) * 2 + c8 * 16;
            const __half* srcA = g_Fh + (size_t)(m0 + row) * G_PAD + kofs + c8 * 8;
            CP_ASYNC16(dstA, srcA);
            uint32_t dstB = bsBase + (buf * B_STAGE_H + row * BKPH) * 2 + c8 * 16;
            const __half* srcB = g_V2h + (size_t)(n0 + row) * G_PAD + kofs + c8 * 8;
            CP_ASYNC16(dstB, srcB);
        }
        CP_COMMIT();
    };

    float c[4][4][4];
    #pragma unroll
    for (int mt = 0; mt < 4; ++mt)
        #pragma unroll
        for (int nt = 0; nt < 4; ++nt)
            #pragma unroll
            for (int j = 0; j < 4; ++j) c[mt][nt][j] = 0.f;

    load_stage(0, 0);
    load_stage(1, 1);
    load_stage(2, 2);

    #pragma unroll 1
    for (int it = 0; it < NIT; ++it) {
        int buf = it % NSTAGES;
        if (it <= NIT - 3)      { CP_WAIT(2); }
        else if (it == NIT - 2) { CP_WAIT(1); }
        else                    { CP_WAIT(0); }
        __syncthreads();
        if (it + 3 < NIT) load_stage(it + 3, (it + 3) % NSTAGES);

        uint32_t aBufBase = asBase + (buf * A_STAGE_H) * 2;
        uint32_t bBufBase = bsBase + (buf * B_STAGE_H) * 2;

        #pragma unroll
        for (int ks = 0; ks < 2; ++ks) {
            uint32_t a[4][4], b[4][2];
            #pragma unroll
            for (int mt = 0; mt < 4; ++mt) {
                int r = warpM * 64 + mt * 16 + rowA_l;
                uint32_t addr = aBufBase + (r * BKPH + ks * 16 + kA_l) * 2;
                LDSM_X4(a[mt][0], a[mt][1], a[mt][2], a[mt][3], addr);
            }
            #pragma unroll
            for (int pr = 0; pr < 2; ++pr) {
                int rb = warpN * 32 + pr * 16 + rowB_l;
                uint32_t addr = bBufBase + (rb * BKPH + ks * 16 + kB_l) * 2;
                LDSM_X4(b[2*pr][0], b[2*pr][1], b[2*pr+1][0], b[2*pr+1][1], addr);
            }
            #pragma unroll
            for (int mt = 0; mt < 4; ++mt)
                #pragma unroll
                for (int nt = 0; nt < 4; ++nt)
                    MMA_F16(c[mt][nt], a[mt], b[nt]);
        }
    }

    // epilogue: atomicAdd into out, pkan layout
    #pragma unroll
    for (int mt = 0; mt < 4; ++mt) {
        int row0 = m0 + warpM * 64 + mt * 16 + gRow;
        #pragma unroll
        for (int nt = 0; nt < 4; ++nt) {
            int col = n0 + warpN * 32 + nt * 8 + gCol * 2;
            if (col < KN_COLS) {
                int k = col >> 3;
                int n = col & 7;
                {
                    int p = row0 >> 2, a = row0 & 3;
                    float* dst = out + ((p * K_DIM + k) * A_CH + a) * N_DIM + n;
                    atomicAdd(dst,     c[mt][nt][0]);
                    atomicAdd(dst + 1, c[mt][nt][1]);
                }
                {
                    int row1 = row0 + 8;
                    int p = row1 >> 2, a = row1 & 3;
                    float* dst = out + ((p * K_DIM + k) * A_CH + a) * N_DIM + n;
                    atomicAdd(dst,     c[mt][nt][2]);
                    atomicAdd(dst + 1, c[mt][nt][3]);
                }
            }
        }
    }
}

// ---------------------------------------------------------------------------
extern "C" void kernel_launch(void* const* d_in, const int* in_sizes, int n_in,
                              void* d_out, int out_size) {
    const float* positions = (const float*)d_in[0];
    const float* mesh      = (const float*)d_in[1];
    const float* cell      = (const float*)d_in[2];
    const float* values    = (const float*)d_in[3];
    const float* weights   = (const float*)d_in[4];
    const float* grid      = (const float*)d_in[5];
    float* out = (float*)d_out;
    (void)in_sizes; (void)n_in;

    cudaFuncSetAttribute(gemm_mma_kernel,
                         cudaFuncAttributeMaxDynamicSharedMemorySize, SMEM_BYTES);

    sort_kernel<<<1, 1024>>>(grid, cell);
    prep_kernel<<<(KN_COLS * G_PTS + 255) / 256, 256>>>(mesh, values, weights, grid);
    interp_kernel<<<(P_ATOMS * G_PTS + 255) / 256, 256>>>(positions);

    cudaMemsetAsync(out, 0, (size_t)out_size * sizeof(float));

    dim3 ggrid(KN_PAD / BN, M_ROWS / BM, KSPLIT);   // (4, 16, 4)
    gemm_mma_kernel<<<ggrid, 256, SMEM_BYTES>>>(out);
}

// round 12
// speedup vs baseline: 1.0206x; 1.0206x over previous
#include <cuda_runtime.h>
#include <cuda_fp16.h>
#include <cstdint>

// ---------------------------------------------------------------------------
// Problem constants
// ---------------------------------------------------------------------------
#define P_ATOMS 512
#define A_CH    4
#define K_DIM   49
#define N_DIM   8
#define NM      128
#define NM2     (NM*NM)
#define NM3     (NM*NM*NM)
#define NB      64              // blocks per dim (Morton-2)
#define G_PTS   1900
#define G_PAD   1920
#define G_SORT  2048            // bitonic size
#define M_ROWS  (P_ATOMS*A_CH)  // 2048
#define KN_COLS (K_DIM*N_DIM)   // 392
#define KN_PAD  512             // 4 * 128

#define KSPLIT  2
#define KCHUNK  960             // 2*960 = 1920
#define BM      128
#define BN      128
#define BK      32
#define NIT     (KCHUNK/BK)     // 30
#define BKPH    (BK + 8)        // padded row stride in halves (40 -> 80 B rows)
#define NSTAGES 4

#define A_STAGE_H (BM * BKPH)           // 5120 halves
#define B_STAGE_H (BN * BKPH)           // 5120 halves
#define SMEM_BYTES (NSTAGES * (A_STAGE_H + B_STAGE_H) * 2)   // 81920 B

// ---------------------------------------------------------------------------
// Device scratch (zero-initialized at module load; pads never written)
// ---------------------------------------------------------------------------
__device__ __half g_Fh[M_ROWS * G_PAD];              // 7.9 MB
__device__ __half g_V2h[KN_PAD * G_PAD];             // 2.0 MB
__device__ __align__(128) uint2 g_meshT[NM3];        // 16.8 MB  fp16x4, Morton-2
__device__ float  g_w2[G_PTS];
__device__ float4 g_grid2[G_PTS];
__device__ float  g_inv[9];
__device__ uint32_t g_perm[G_SORT];                  // g2 -> original g

// ---------------------------------------------------------------------------
// helpers
// ---------------------------------------------------------------------------
#define CP_ASYNC16(dst, src) \
    asm volatile("cp.async.cg.shared.global [%0], [%1], 16;" :: "r"(dst), "l"(src) : "memory")
#define CP_COMMIT() asm volatile("cp.async.commit_group;" ::: "memory")
#define CP_WAIT(n)  asm volatile("cp.async.wait_group %0;" :: "n"(n) : "memory")

#define MMA_F16(c, a, b) \
    asm volatile("mma.sync.aligned.m16n8k16.row.col.f32.f16.f16.f32 " \
        "{%0,%1,%2,%3}, {%4,%5,%6,%7}, {%8,%9}, {%0,%1,%2,%3};" \
        : "+f"((c)[0]), "+f"((c)[1]), "+f"((c)[2]), "+f"((c)[3]) \
        : "r"((a)[0]), "r"((a)[1]), "r"((a)[2]), "r"((a)[3]), \
          "r"((b)[0]), "r"((b)[1]))

#define LDSM_X4(r0, r1, r2, r3, addr) \
    asm volatile("ldmatrix.sync.aligned.m8n8.x4.shared.b16 {%0,%1,%2,%3}, [%4];" \
        : "=r"(r0), "=r"(r1), "=r"(r2), "=r"(r3) : "r"(addr))

__device__ __forceinline__ uint32_t pack_h2(float a, float b) {
    __half2 h = __floats2half2_rn(a, b);
    return *reinterpret_cast<uint32_t*>(&h);
}

__device__ __forceinline__ uint32_t expand_bits3(uint32_t x) {
    x &= 0x3FF;
    x = (x | (x << 16)) & 0x030000FF;
    x = (x | (x << 8))  & 0x0300F00F;
    x = (x | (x << 4))  & 0x030C30C3;
    x = (x | (x << 2))  & 0x09249249;
    return x;
}

// ---------------------------------------------------------------------------
// Kernel 0: sort grid points by Morton code of their cell-block coordinate.
// Single block, 1024 threads, bitonic sort of 2048 packed (key|idx) words.
// Also computes the cell inverse.
// ---------------------------------------------------------------------------
__global__ void __launch_bounds__(1024)
sort_kernel(const float* __restrict__ grid, const float* __restrict__ cell) {
    __shared__ uint32_t s[G_SORT];
    int tid = threadIdx.x;

    __shared__ float sinv[9];
    if (tid == 0) {
        float c00 = cell[0], c01 = cell[1], c02 = cell[2];
        float c10 = cell[3], c11 = cell[4], c12 = cell[5];
        float c20 = cell[6], c21 = cell[7], c22 = cell[8];
        float m00 = c11*c22 - c12*c21;
        float m01 = c02*c21 - c01*c22;
        float m02 = c01*c12 - c02*c11;
        float m10 = c12*c20 - c10*c22;
        float m11 = c00*c22 - c02*c20;
        float m12 = c02*c10 - c00*c12;
        float m20 = c10*c21 - c11*c20;
        float m21 = c01*c20 - c00*c21;
        float m22 = c00*c11 - c01*c10;
        float rdet = 1.0f / (c00*m00 + c01*m10 + c02*m20);
        sinv[0] = m00*rdet; sinv[1] = m01*rdet; sinv[2] = m02*rdet;
        sinv[3] = m10*rdet; sinv[4] = m11*rdet; sinv[5] = m12*rdet;
        sinv[6] = m20*rdet; sinv[7] = m21*rdet; sinv[8] = m22*rdet;
        g_inv[0]=sinv[0]; g_inv[1]=sinv[1]; g_inv[2]=sinv[2];
        g_inv[3]=sinv[3]; g_inv[4]=sinv[4]; g_inv[5]=sinv[5];
        g_inv[6]=sinv[6]; g_inv[7]=sinv[7]; g_inv[8]=sinv[8];
    }
    __syncthreads();

    for (int i = tid; i < G_SORT; i += 1024) {
        uint32_t key;
        if (i < G_PTS) {
            float gx = __ldg(grid + i*3 + 0);
            float gy = __ldg(grid + i*3 + 1);
            float gz = __ldg(grid + i*3 + 2);
            float ux = (gx*sinv[0] + gy*sinv[3] + gz*sinv[6]) * (float)NM;
            float uy = (gx*sinv[1] + gy*sinv[4] + gz*sinv[7]) * (float)NM;
            float uz = (gx*sinv[2] + gy*sinv[5] + gz*sinv[8]) * (float)NM;
            uint32_t bx = ((uint32_t)(int)(floorf(ux) + 128.f)) >> 1;
            uint32_t by = ((uint32_t)(int)(floorf(uy) + 128.f)) >> 1;
            uint32_t bz = ((uint32_t)(int)(floorf(uz) + 128.f)) >> 1;
            uint32_t m = expand_bits3(bx) | (expand_bits3(by) << 1) | (expand_bits3(bz) << 2);
            key = (m << 11) | (uint32_t)i;
        } else {
            key = 0xFFFFFFFFu;
        }
        s[i] = key;
    }
    __syncthreads();

    for (int k = 2; k <= G_SORT; k <<= 1) {
        for (int j = k >> 1; j > 0; j >>= 1) {
            int t = tid;
            int i = ((t & ~(j - 1)) << 1) | (t & (j - 1));
            int p = i | j;
            bool up = ((i & k) == 0);
            uint32_t a = s[i], b = s[p];
            if ((a > b) == up) { s[i] = b; s[p] = a; }
            __syncthreads();
        }
    }

    for (int i = tid; i < G_SORT; i += 1024)
        g_perm[i] = s[i] & 0x7FFu;
}

// ---------------------------------------------------------------------------
// Kernel A: prep (Morton block transpose -> fp16, V2/weights/grid permute)
// ---------------------------------------------------------------------------
__global__ void __launch_bounds__(256)
prep_kernel(const float* __restrict__ mesh,
            const float* __restrict__ values,
            const float* __restrict__ weights,
            const float* __restrict__ grid) {
    int i = blockIdx.x * blockDim.x + threadIdx.x;
    if (i < NB*NB*NB) {
        int bz = i & 63, by = (i >> 6) & 63, bx = i >> 12;
        uint2 cells[8];
        #pragma unroll
        for (int jx = 0; jx < 2; ++jx) {
            #pragma unroll
            for (int jy = 0; jy < 2; ++jy) {
                int x = 2*bx + jx, y = 2*by + jy;
                const float* base = mesh + ((size_t)x * NM + y) * NM + 2*bz;
                float2 f0 = __ldg((const float2*)(base));
                float2 f1 = __ldg((const float2*)(base + NM3));
                float2 f2 = __ldg((const float2*)(base + 2*NM3));
                float2 f3 = __ldg((const float2*)(base + 3*NM3));
                int o = jx*4 + jy*2;
                cells[o    ] = make_uint2(pack_h2(f0.x, f1.x), pack_h2(f2.x, f3.x));
                cells[o + 1] = make_uint2(pack_h2(f0.y, f1.y), pack_h2(f2.y, f3.y));
            }
        }
        uint4* dst = reinterpret_cast<uint4*>(g_meshT + (size_t)i * 8);
        const uint4* src = reinterpret_cast<const uint4*>(cells);
        dst[0] = src[0]; dst[1] = src[1]; dst[2] = src[2]; dst[3] = src[3];
    }
    if (i < KN_COLS * G_PTS) {
        int row = i / G_PTS;
        int g2  = i - row * G_PTS;
        int g   = (int)g_perm[g2];
        g_V2h[row * G_PAD + g2] = __float2half_rn(__ldg(values + row * G_PTS + g));
    }
    if (i < G_PTS) {
        int g = (int)g_perm[i];
        g_w2[i] = __ldg(weights + g);
        float4 gp;
        gp.x = __ldg(grid + g*3 + 0);
        gp.y = __ldg(grid + g*3 + 1);
        gp.z = __ldg(grid + g*3 + 2);
        gp.w = 0.f;
        g_grid2[i] = gp;
    }
}

// ---------------------------------------------------------------------------
// Kernel B: B-spline interpolation -> fp16 F[(p,a)][g2]
// 18 LDG.128 batched (MLP=18); warp lanes are Morton-adjacent grid points.
// ---------------------------------------------------------------------------
__global__ void __launch_bounds__(256)
interp_kernel(const float* __restrict__ pos) {
    int tid = blockIdx.x * blockDim.x + threadIdx.x;
    if (tid >= P_ATOMS * G_PTS) return;
    int p  = tid / G_PTS;
    int g2 = tid - p * G_PTS;

    float m00 = g_inv[0], m01 = g_inv[1], m02 = g_inv[2];
    float m10 = g_inv[3], m11 = g_inv[4], m12 = g_inv[5];
    float m20 = g_inv[6], m21 = g_inv[7], m22 = g_inv[8];

    float4 gp = g_grid2[g2];
    float px = __ldg(pos + p*3 + 0) + gp.x;
    float py = __ldg(pos + p*3 + 1) + gp.y;
    float pz = __ldg(pos + p*3 + 2) + gp.z;

    float fx = px*m00 + py*m10 + pz*m20;
    float fy = px*m01 + py*m11 + pz*m21;
    float fz = px*m02 + py*m12 + pz*m22;

    float wx[3], wy[3];
    int xpart[3], ypart[3];
    {
        float u = fx * (float)NM, nf = floorf(u + 0.5f), x = u - nf;
        wx[0] = 0.5f*(0.5f-x)*(0.5f-x); wx[1] = 0.75f - x*x; wx[2] = 0.5f*(0.5f+x)*(0.5f+x);
        int n = (int)nf;
        #pragma unroll
        for (int d = 0; d < 3; ++d) {
            int v = (n + d - 1 + 4*NM) & (NM-1);
            xpart[d] = (v >> 1) * 16384 + (v & 1) * 2;
        }
    }
    {
        float u = fy * (float)NM, nf = floorf(u + 0.5f), x = u - nf;
        wy[0] = 0.5f*(0.5f-x)*(0.5f-x); wy[1] = 0.75f - x*x; wy[2] = 0.5f*(0.5f+x)*(0.5f+x);
        int n = (int)nf;
        #pragma unroll
        for (int d = 0; d < 3; ++d) {
            int v = (n + d - 1 + 4*NM) & (NM-1);
            ypart[d] = (v >> 1) * 256 + (v & 1);
        }
    }
    int zpart[2];
    float zwA[2], zwB[2];
    {
        float u = fz * (float)NM, nf = floorf(u + 0.5f), x = u - nf;
        float wz0 = 0.5f*(0.5f-x)*(0.5f-x);
        float wz1 = 0.75f - x*x;
        float wz2 = 0.5f*(0.5f+x)*(0.5f+x);
        int nn = (int)nf + 4*NM;
        int b_lo = ((nn - 1) & (NM-1)) >> 1;
        int b_hi = ((nn + 1) & (NM-1)) >> 1;
        zpart[0] = b_lo * 4;
        zpart[1] = b_hi * 4;
        bool odd = (nn & 1) != 0;
        zwA[0] = odd ? wz0 : 0.f;
        zwB[0] = odd ? wz1 : wz0;
        zwA[1] = odd ? wz2 : wz1;
        zwB[1] = odd ? 0.f : wz2;
    }

    const uint4* mesh4 = reinterpret_cast<const uint4*>(g_meshT);

    uint4 v[18];
    #pragma unroll
    for (int dx = 0; dx < 3; ++dx)
        #pragma unroll
        for (int dy = 0; dy < 3; ++dy)
            #pragma unroll
            for (int dz = 0; dz < 2; ++dz)
                v[(dx*3 + dy)*2 + dz] = __ldg(mesh4 + xpart[dx] + ypart[dy] + zpart[dz]);

    float acc0 = 0.f, acc1 = 0.f, acc2 = 0.f, acc3 = 0.f;
    #pragma unroll
    for (int dx = 0; dx < 3; ++dx) {
        #pragma unroll
        for (int dy = 0; dy < 3; ++dy) {
            float wxy = wx[dx] * wy[dy];
            #pragma unroll
            for (int dz = 0; dz < 2; ++dz) {
                uint4 q = v[(dx*3 + dy)*2 + dz];
                float wA = wxy * zwA[dz];
                float wB = wxy * zwB[dz];
                float2 a01 = __half22float2(*reinterpret_cast<__half2*>(&q.x));
                float2 a23 = __half22float2(*reinterpret_cast<__half2*>(&q.y));
                float2 b01 = __half22float2(*reinterpret_cast<__half2*>(&q.z));
                float2 b23 = __half22float2(*reinterpret_cast<__half2*>(&q.w));
                acc0 += wA * a01.x + wB * b01.x;
                acc1 += wA * a01.y + wB * b01.y;
                acc2 += wA * a23.x + wB * b23.x;
                acc3 += wA * a23.y + wB * b23.y;
            }
        }
    }

    float wt = g_w2[g2];
    g_Fh[(p*A_CH + 0)*G_PAD + g2] = __float2half_rn(acc0 * wt);
    g_Fh[(p*A_CH + 1)*G_PAD + g2] = __float2half_rn(acc1 * wt);
    g_Fh[(p*A_CH + 2)*G_PAD + g2] = __float2half_rn(acc2 * wt);
    g_Fh[(p*A_CH + 3)*G_PAD + g2] = __float2half_rn(acc3 * wt);
}

// ---------------------------------------------------------------------------
// Kernel C: fp16 mma.sync GEMM with ldmatrix, 4-stage cp.async, split-K 2.
// Block 128x128, BK=32, 8 warps (warp tile 64x32), grid (4,16,2) = one wave.
// ---------------------------------------------------------------------------
__global__ void __launch_bounds__(256, 1)
gemm_mma_kernel(float* __restrict__ out) {
    extern __shared__ __half smemh[];
    __half* As = smemh;                          // [4][BM][BKPH]
    __half* Bs = smemh + NSTAGES * A_STAGE_H;    // [4][BN][BKPH]

    const int tid  = threadIdx.x;
    const int lane = tid & 31;
    const int wid  = tid >> 5;
    const int warpM = wid & 1;
    const int warpN = wid >> 1;
    const int gRow = lane >> 2;
    const int gCol = lane & 3;

    const int n0    = blockIdx.x * BN;
    const int m0    = blockIdx.y * BM;
    const int bz    = blockIdx.z;
    const int kbase = bz * KCHUNK;

    uint32_t asBase = (uint32_t)__cvta_generic_to_shared(As);
    uint32_t bsBase = (uint32_t)__cvta_generic_to_shared(Bs);

    const int rowA_l = (lane & 7) + (((lane >> 3) & 1) << 3);
    const int kA_l   = (lane >> 4) << 3;
    const int rowB_l = (lane & 7) + ((lane >> 4) << 3);
    const int kB_l   = ((lane >> 3) & 1) << 3;

    auto load_stage = [&](int it, int buf) {
        int kofs = kbase + it * BK;
        #pragma unroll
        for (int i = 0; i < 2; ++i) {
            int e   = tid + i * 256;
            int row = e >> 2;
            int c8  = e & 3;
            uint32_t dstA = asBase + (buf * A_STAGE_H + row * BKPH) * 2 + c8 * 16;
            const __half* srcA = g_Fh + (size_t)(m0 + row) * G_PAD + kofs + c8 * 8;
            CP_ASYNC16(dstA, srcA);
            uint32_t dstB = bsBase + (buf * B_STAGE_H + row * BKPH) * 2 + c8 * 16;
            const __half* srcB = g_V2h + (size_t)(n0 + row) * G_PAD + kofs + c8 * 8;
            CP_ASYNC16(dstB, srcB);
        }
        CP_COMMIT();
    };

    float c[4][4][4];
    #pragma unroll
    for (int mt = 0; mt < 4; ++mt)
        #pragma unroll
        for (int nt = 0; nt < 4; ++nt)
            #pragma unroll
            for (int j = 0; j < 4; ++j) c[mt][nt][j] = 0.f;

    load_stage(0, 0);
    load_stage(1, 1);
    load_stage(2, 2);

    #pragma unroll 1
    for (int it = 0; it < NIT; ++it) {
        int buf = it % NSTAGES;
        if (it <= NIT - 3)      { CP_WAIT(2); }
        else if (it == NIT - 2) { CP_WAIT(1); }
        else                    { CP_WAIT(0); }
        __syncthreads();
        if (it + 3 < NIT) load_stage(it + 3, (it + 3) % NSTAGES);

        uint32_t aBufBase = asBase + (buf * A_STAGE_H) * 2;
        uint32_t bBufBase = bsBase + (buf * B_STAGE_H) * 2;

        #pragma unroll
        for (int ks = 0; ks < 2; ++ks) {
            uint32_t a[4][4], b[4][2];
            #pragma unroll
            for (int mt = 0; mt < 4; ++mt) {
                int r = warpM * 64 + mt * 16 + rowA_l;
                uint32_t addr = aBufBase + (r * BKPH + ks * 16 + kA_l) * 2;
                LDSM_X4(a[mt][0], a[mt][1], a[mt][2], a[mt][3], addr);
            }
            #pragma unroll
            for (int pr = 0; pr < 2; ++pr) {
                int rb = warpN * 32 + pr * 16 + rowB_l;
                uint32_t addr = bBufBase + (rb * BKPH + ks * 16 + kB_l) * 2;
                LDSM_X4(b[2*pr][0], b[2*pr][1], b[2*pr+1][0], b[2*pr+1][1], addr);
            }
            #pragma unroll
            for (int mt = 0; mt < 4; ++mt)
                #pragma unroll
                for (int nt = 0; nt < 4; ++nt)
                    MMA_F16(c[mt][nt], a[mt], b[nt]);
        }
    }

    // epilogue: atomicAdd into out, pkan layout
    #pragma unroll
    for (int mt = 0; mt < 4; ++mt) {
        int row0 = m0 + warpM * 64 + mt * 16 + gRow;
        #pragma unroll
        for (int nt = 0; nt < 4; ++nt) {
            int col = n0 + warpN * 32 + nt * 8 + gCol * 2;
            if (col < KN_COLS) {
                int k = col >> 3;
                int n = col & 7;
                {
                    int p = row0 >> 2, a = row0 & 3;
                    float* dst = out + ((p * K_DIM + k) * A_CH + a) * N_DIM + n;
                    atomicAdd(dst,     c[mt][nt][0]);
                    atomicAdd(dst + 1, c[mt][nt][1]);
                }
                {
                    int row1 = row0 + 8;
                    int p = row1 >> 2, a = row1 & 3;
                    float* dst = out + ((p * K_DIM + k) * A_CH + a) * N_DIM + n;
                    atomicAdd(dst,     c[mt][nt][2]);
                    atomicAdd(dst + 1, c[mt][nt][3]);
                }
            }
        }
    }
}

// ---------------------------------------------------------------------------
extern "C" void kernel_launch(void* const* d_in, const int* in_sizes, int n_in,
                              void* d_out, int out_size) {
    const float* positions = (const float*)d_in[0];
    const float* mesh      = (const float*)d_in[1];
    const float* cell      = (const float*)d_in[2];
    const float* values    = (const float*)d_in[3];
    const float* weights   = (const float*)d_in[4];
    const float* grid      = (const float*)d_in[5];
    float* out = (float*)d_out;
    (void)in_sizes; (void)n_in;

    cudaFuncSetAttribute(gemm_mma_kernel,
                         cudaFuncAttributeMaxDynamicSharedMemorySize, SMEM_BYTES);

    sort_kernel<<<1, 1024>>>(grid, cell);
    prep_kernel<<<(KN_COLS * G_PTS + 255) / 256, 256>>>(mesh, values, weights, grid);
    interp_kernel<<<(P_ATOMS * G_PTS + 255) / 256, 256>>>(positions);

    cudaMemsetAsync(out, 0, (size_t)out_size * sizeof(float));

    dim3 ggrid(KN_PAD / BN, M_ROWS / BM, KSPLIT);   // (4, 16, 2)
    gemm_mma_kernel<<<ggrid, 256, SMEM_BYTES>>>(out);
}

// round 13
// speedup vs baseline: 1.1709x; 1.1473x over previous
#include <cuda_runtime.h>
#include <cuda_fp16.h>
#include <cstdint>

// ---------------------------------------------------------------------------
// Problem constants
// ---------------------------------------------------------------------------
#define P_ATOMS 512
#define A_CH    4
#define K_DIM   49
#define N_DIM   8
#define NM      128
#define NM2     (NM*NM)
#define NM3     (NM*NM*NM)
#define NB      64              // blocks per dim (Morton-2 mesh layout)
#define G_PTS   1900
#define G_PAD   1920
#define N_RAD   50
#define N_ANG   38
#define M_ROWS  (P_ATOMS*A_CH)  // 2048
#define KN_COLS (K_DIM*N_DIM)   // 392
#define KN_PAD  448             // 7 * 64

#define KSPLIT  2
#define KCHUNK  960             // 2*960 = 1920
#define BM      128
#define BN      64
#define BK      32
#define NIT     (KCHUNK/BK)     // 30
#define BKPH    (BK + 8)        // padded row stride in halves (40 -> 80 B rows)
#define NSTAGES 4

#define A_STAGE_H (BM * BKPH)           // 5120 halves
#define B_STAGE_H (BN * BKPH)           // 2560 halves
#define SMEM_BYTES (NSTAGES * (A_STAGE_H + B_STAGE_H) * 2)   // 61440 B

// ---------------------------------------------------------------------------
// Device scratch (zero-initialized at module load; pads never written)
// ---------------------------------------------------------------------------
__device__ __half g_Fh[M_ROWS * G_PAD];              // 7.9 MB
__device__ __half g_V2h[KN_PAD * G_PAD];             // 1.7 MB
__device__ __align__(128) uint2 g_meshT[NM3];        // 16.8 MB  fp16x4, Morton-2
__device__ float  g_w2[G_PTS];
__device__ float4 g_grid2[G_PTS];
__device__ float  g_inv[9];

// ---------------------------------------------------------------------------
// helpers
// ---------------------------------------------------------------------------
#define CP_ASYNC16(dst, src) \
    asm volatile("cp.async.cg.shared.global [%0], [%1], 16;" :: "r"(dst), "l"(src) : "memory")
#define CP_COMMIT() asm volatile("cp.async.commit_group;" ::: "memory")
#define CP_WAIT(n)  asm volatile("cp.async.wait_group %0;" :: "n"(n) : "memory")

#define MMA_F16(c, a, b) \
    asm volatile("mma.sync.aligned.m16n8k16.row.col.f32.f16.f16.f32 " \
        "{%0,%1,%2,%3}, {%4,%5,%6,%7}, {%8,%9}, {%0,%1,%2,%3};" \
        : "+f"((c)[0]), "+f"((c)[1]), "+f"((c)[2]), "+f"((c)[3]) \
        : "r"((a)[0]), "r"((a)[1]), "r"((a)[2]), "r"((a)[3]), \
          "r"((b)[0]), "r"((b)[1]))

#define LDSM_X4(r0, r1, r2, r3, addr) \
    asm volatile("ldmatrix.sync.aligned.m8n8.x4.shared.b16 {%0,%1,%2,%3}, [%4];" \
        : "=r"(r0), "=r"(r1), "=r"(r2), "=r"(r3) : "r"(addr))

__device__ __forceinline__ uint32_t pack_h2(float a, float b) {
    __half2 h = __floats2half2_rn(a, b);
    return *reinterpret_cast<uint32_t*>(&h);
}

// g2 = ang*50 + r   <->   g = r*38 + ang   (ray order — verified best)
__device__ __forceinline__ int g_from_g2(int g2) {
    int ang = g2 / N_RAD;
    int r   = g2 - ang * N_RAD;
    return r * N_ANG + ang;
}

// ---------------------------------------------------------------------------
// Kernel A: prep (Morton block transpose -> fp16, V2/weights/grid permute,
// cell inverse)
// ---------------------------------------------------------------------------
__global__ void __launch_bounds__(256)
prep_kernel(const float* __restrict__ mesh,
            const float* __restrict__ values,
            const float* __restrict__ weights,
            const float* __restrict__ grid,
            const float* __restrict__ cell) {
    int i = blockIdx.x * blockDim.x + threadIdx.x;
    if (i < NB*NB*NB) {
        int bz = i & 63, by = (i >> 6) & 63, bx = i >> 12;
        uint2 cells[8];
        #pragma unroll
        for (int jx = 0; jx < 2; ++jx) {
            #pragma unroll
            for (int jy = 0; jy < 2; ++jy) {
                int x = 2*bx + jx, y = 2*by + jy;
                const float* base = mesh + ((size_t)x * NM + y) * NM + 2*bz;
                float2 f0 = __ldg((const float2*)(base));
                float2 f1 = __ldg((const float2*)(base + NM3));
                float2 f2 = __ldg((const float2*)(base + 2*NM3));
                float2 f3 = __ldg((const float2*)(base + 3*NM3));
                int o = jx*4 + jy*2;
                cells[o    ] = make_uint2(pack_h2(f0.x, f1.x), pack_h2(f2.x, f3.x));
                cells[o + 1] = make_uint2(pack_h2(f0.y, f1.y), pack_h2(f2.y, f3.y));
            }
        }
        uint4* dst = reinterpret_cast<uint4*>(g_meshT + (size_t)i * 8);
        const uint4* src = reinterpret_cast<const uint4*>(cells);
        dst[0] = src[0]; dst[1] = src[1]; dst[2] = src[2]; dst[3] = src[3];
    }
    if (i < KN_COLS * G_PTS) {
        int row = i / G_PTS;
        int g2  = i - row * G_PTS;
        g_V2h[row * G_PAD + g2] = __float2half_rn(__ldg(values + row * G_PTS + g_from_g2(g2)));
    }
    if (i < G_PTS) {
        int g = g_from_g2(i);
        g_w2[i] = __ldg(weights + g);
        float4 gp;
        gp.x = __ldg(grid + g*3 + 0);
        gp.y = __ldg(grid + g*3 + 1);
        gp.z = __ldg(grid + g*3 + 2);
        gp.w = 0.f;
        g_grid2[i] = gp;
    }
    if (i == 0) {
        float c00 = cell[0], c01 = cell[1], c02 = cell[2];
        float c10 = cell[3], c11 = cell[4], c12 = cell[5];
        float c20 = cell[6], c21 = cell[7], c22 = cell[8];
        float m00 = c11*c22 - c12*c21;
        float m01 = c02*c21 - c01*c22;
        float m02 = c01*c12 - c02*c11;
        float m10 = c12*c20 - c10*c22;
        float m11 = c00*c22 - c02*c20;
        float m12 = c02*c10 - c00*c12;
        float m20 = c10*c21 - c11*c20;
        float m21 = c01*c20 - c00*c21;
        float m22 = c00*c11 - c01*c10;
        float rdet = 1.0f / (c00*m00 + c01*m10 + c02*m20);
        g_inv[0] = m00*rdet; g_inv[1] = m01*rdet; g_inv[2] = m02*rdet;
        g_inv[3] = m10*rdet; g_inv[4] = m11*rdet; g_inv[5] = m12*rdet;
        g_inv[6] = m20*rdet; g_inv[7] = m21*rdet; g_inv[8] = m22*rdet;
    }
}

// ---------------------------------------------------------------------------
// Kernel B: B-spline interpolation -> fp16 F[(p,a)][g2]
// 18 LDG.128 batched (MLP=18); ray-ordered lanes (verified best locality).
// ---------------------------------------------------------------------------
__global__ void __launch_bounds__(256)
interp_kernel(const float* __restrict__ pos) {
    int tid = blockIdx.x * blockDim.x + threadIdx.x;
    if (tid >= P_ATOMS * G_PTS) return;
    int p  = tid / G_PTS;
    int g2 = tid - p * G_PTS;

    float m00 = g_inv[0], m01 = g_inv[1], m02 = g_inv[2];
    float m10 = g_inv[3], m11 = g_inv[4], m12 = g_inv[5];
    float m20 = g_inv[6], m21 = g_inv[7], m22 = g_inv[8];

    float4 gp = g_grid2[g2];
    float px = __ldg(pos + p*3 + 0) + gp.x;
    float py = __ldg(pos + p*3 + 1) + gp.y;
    float pz = __ldg(pos + p*3 + 2) + gp.z;

    float fx = px*m00 + py*m10 + pz*m20;
    float fy = px*m01 + py*m11 + pz*m21;
    float fz = px*m02 + py*m12 + pz*m22;

    float wx[3], wy[3];
    int xpart[3], ypart[3];
    {
        float u = fx * (float)NM, nf = floorf(u + 0.5f), x = u - nf;
        wx[0] = 0.5f*(0.5f-x)*(0.5f-x); wx[1] = 0.75f - x*x; wx[2] = 0.5f*(0.5f+x)*(0.5f+x);
        int n = (int)nf;
        #pragma unroll
        for (int d = 0; d < 3; ++d) {
            int v = (n + d - 1 + 4*NM) & (NM-1);
            xpart[d] = (v >> 1) * 16384 + (v & 1) * 2;
        }
    }
    {
        float u = fy * (float)NM, nf = floorf(u + 0.5f), x = u - nf;
        wy[0] = 0.5f*(0.5f-x)*(0.5f-x); wy[1] = 0.75f - x*x; wy[2] = 0.5f*(0.5f+x)*(0.5f+x);
        int n = (int)nf;
        #pragma unroll
        for (int d = 0; d < 3; ++d) {
            int v = (n + d - 1 + 4*NM) & (NM-1);
            ypart[d] = (v >> 1) * 256 + (v & 1);
        }
    }
    int zpart[2];
    float zwA[2], zwB[2];
    {
        float u = fz * (float)NM, nf = floorf(u + 0.5f), x = u - nf;
        float wz0 = 0.5f*(0.5f-x)*(0.5f-x);
        float wz1 = 0.75f - x*x;
        float wz2 = 0.5f*(0.5f+x)*(0.5f+x);
        int nn = (int)nf + 4*NM;
        int b_lo = ((nn - 1) & (NM-1)) >> 1;
        int b_hi = ((nn + 1) & (NM-1)) >> 1;
        zpart[0] = b_lo * 4;
        zpart[1] = b_hi * 4;
        bool odd = (nn & 1) != 0;
        zwA[0] = odd ? wz0 : 0.f;
        zwB[0] = odd ? wz1 : wz0;
        zwA[1] = odd ? wz2 : wz1;
        zwB[1] = odd ? 0.f : wz2;
    }

    const uint4* mesh4 = reinterpret_cast<const uint4*>(g_meshT);

    uint4 v[18];
    #pragma unroll
    for (int dx = 0; dx < 3; ++dx)
        #pragma unroll
        for (int dy = 0; dy < 3; ++dy)
            #pragma unroll
            for (int dz = 0; dz < 2; ++dz)
                v[(dx*3 + dy)*2 + dz] = __ldg(mesh4 + xpart[dx] + ypart[dy] + zpart[dz]);

    float acc0 = 0.f, acc1 = 0.f, acc2 = 0.f, acc3 = 0.f;
    #pragma unroll
    for (int dx = 0; dx < 3; ++dx) {
        #pragma unroll
        for (int dy = 0; dy < 3; ++dy) {
            float wxy = wx[dx] * wy[dy];
            #pragma unroll
            for (int dz = 0; dz < 2; ++dz) {
                uint4 q = v[(dx*3 + dy)*2 + dz];
                float wA = wxy * zwA[dz];
                float wB = wxy * zwB[dz];
                float2 a01 = __half22float2(*reinterpret_cast<__half2*>(&q.x));
                float2 a23 = __half22float2(*reinterpret_cast<__half2*>(&q.y));
                float2 b01 = __half22float2(*reinterpret_cast<__half2*>(&q.z));
                float2 b23 = __half22float2(*reinterpret_cast<__half2*>(&q.w));
                acc0 += wA * a01.x + wB * b01.x;
                acc1 += wA * a01.y + wB * b01.y;
                acc2 += wA * a23.x + wB * b23.x;
                acc3 += wA * a23.y + wB * b23.y;
            }
        }
    }

    float wt = g_w2[g2];
    g_Fh[(p*A_CH + 0)*G_PAD + g2] = __float2half_rn(acc0 * wt);
    g_Fh[(p*A_CH + 1)*G_PAD + g2] = __float2half_rn(acc1 * wt);
    g_Fh[(p*A_CH + 2)*G_PAD + g2] = __float2half_rn(acc2 * wt);
    g_Fh[(p*A_CH + 3)*G_PAD + g2] = __float2half_rn(acc3 * wt);
}

// ---------------------------------------------------------------------------
// Kernel C: fp16 mma.sync GEMM with ldmatrix, 4-stage cp.async, split-K 2.
// Block 128x64, BK=32, 8 warps (warp tile 32x32), grid (7,16,2) = 224 CTAs,
// 2 CTAs/SM (61.4 KB smem, <=128 regs). atomicAdd epilogue.
// ---------------------------------------------------------------------------
__global__ void __launch_bounds__(256, 2)
gemm_mma_kernel(float* __restrict__ out) {
    extern __shared__ __half smemh[];
    __half* As = smemh;                          // [4][BM][BKPH]
    __half* Bs = smemh + NSTAGES * A_STAGE_H;    // [4][BN][BKPH]

    const int tid  = threadIdx.x;
    const int lane = tid & 31;
    const int wid  = tid >> 5;
    const int warpM = wid & 3;    // 4 warps over M (32 rows each)
    const int warpN = wid >> 2;   // 2 warps over N (32 cols each)
    const int gRow = lane >> 2;
    const int gCol = lane & 3;

    const int n0    = blockIdx.x * BN;
    const int m0    = blockIdx.y * BM;
    const int bz    = blockIdx.z;
    const int kbase = bz * KCHUNK;

    uint32_t asBase = (uint32_t)__cvta_generic_to_shared(As);
    uint32_t bsBase = (uint32_t)__cvta_generic_to_shared(Bs);

    const int rowA_l = (lane & 7) + (((lane >> 3) & 1) << 3);
    const int kA_l   = (lane >> 4) << 3;
    const int rowB_l = (lane & 7) + ((lane >> 4) << 3);
    const int kB_l   = ((lane >> 3) & 1) << 3;

    // one stage: A = 512 cp16 (2/thread), B = 256 cp16 (1/thread)
    auto load_stage = [&](int it, int buf) {
        int kofs = kbase + it * BK;
        #pragma unroll
        for (int i = 0; i < 2; ++i) {
            int e   = tid + i * 256;
            int row = e >> 2;
            int c8  = e & 3;
            uint32_t dstA = asBase + (buf * A_STAGE_H + row * BKPH) * 2 + c8 * 16;
            const __half* srcA = g_Fh + (size_t)(m0 + row) * G_PAD + kofs + c8 * 8;
            CP_ASYNC16(dstA, srcA);
        }
        {
            int row = tid >> 2;
            int c8  = tid & 3;
            uint32_t dstB = bsBase + (buf * B_STAGE_H + row * BKPH) * 2 + c8 * 16;
            const __half* srcB = g_V2h + (size_t)(n0 + row) * G_PAD + kofs + c8 * 8;
            CP_ASYNC16(dstB, srcB);
        }
        CP_COMMIT();
    };

    float c[2][4][4];
    #pragma unroll
    for (int mt = 0; mt < 2; ++mt)
        #pragma unroll
        for (int nt = 0; nt < 4; ++nt)
            #pragma unroll
            for (int j = 0; j < 4; ++j) c[mt][nt][j] = 0.f;

    load_stage(0, 0);
    load_stage(1, 1);
    load_stage(2, 2);

    #pragma unroll 1
    for (int it = 0; it < NIT; ++it) {
        int buf = it % NSTAGES;
        if (it <= NIT - 3)      { CP_WAIT(2); }
        else if (it == NIT - 2) { CP_WAIT(1); }
        else                    { CP_WAIT(0); }
        __syncthreads();
        if (it + 3 < NIT) load_stage(it + 3, (it + 3) % NSTAGES);

        uint32_t aBufBase = asBase + (buf * A_STAGE_H) * 2;
        uint32_t bBufBase = bsBase + (buf * B_STAGE_H) * 2;

        #pragma unroll
        for (int ks = 0; ks < 2; ++ks) {
            uint32_t a[2][4], b[4][2];
            #pragma unroll
            for (int mt = 0; mt < 2; ++mt) {
                int r = warpM * 32 + mt * 16 + rowA_l;
                uint32_t addr = aBufBase + (r * BKPH + ks * 16 + kA_l) * 2;
                LDSM_X4(a[mt][0], a[mt][1], a[mt][2], a[mt][3], addr);
            }
            #pragma unroll
            for (int pr = 0; pr < 2; ++pr) {
                int rb = warpN * 32 + pr * 16 + rowB_l;
                uint32_t addr = bBufBase + (rb * BKPH + ks * 16 + kB_l) * 2;
                LDSM_X4(b[2*pr][0], b[2*pr][1], b[2*pr+1][0], b[2*pr+1][1], addr);
            }
            #pragma unroll
            for (int mt = 0; mt < 2; ++mt)
                #pragma unroll
                for (int nt = 0; nt < 4; ++nt)
                    MMA_F16(c[mt][nt], a[mt], b[nt]);
        }
    }

    // epilogue: atomicAdd into out, pkan layout
    #pragma unroll
    for (int mt = 0; mt < 2; ++mt) {
        int row0 = m0 + warpM * 32 + mt * 16 + gRow;
        #pragma unroll
        for (int nt = 0; nt < 4; ++nt) {
            int col = n0 + warpN * 32 + nt * 8 + gCol * 2;
            if (col < KN_COLS) {
                int k = col >> 3;
                int n = col & 7;
                {
                    int p = row0 >> 2, a = row0 & 3;
                    float* dst = out + ((p * K_DIM + k) * A_CH + a) * N_DIM + n;
                    atomicAdd(dst,     c[mt][nt][0]);
                    atomicAdd(dst + 1, c[mt][nt][1]);
                }
                {
                    int row1 = row0 + 8;
                    int p = row1 >> 2, a = row1 & 3;
                    float* dst = out + ((p * K_DIM + k) * A_CH + a) * N_DIM + n;
                    atomicAdd(dst,     c[mt][nt][2]);
                    atomicAdd(dst + 1, c[mt][nt][3]);
                }
            }
        }
    }
}

// ---------------------------------------------------------------------------
extern "C" void kernel_launch(void* const* d_in, const int* in_sizes, int n_in,
                              void* d_out, int out_size) {
    const float* positions = (const float*)d_in[0];
    const float* mesh      = (const float*)d_in[1];
    const float* cell      = (const float*)d_in[2];
    const float* values    = (const float*)d_in[3];
    const float* weights   = (const float*)d_in[4];
    const float* grid      = (const float*)d_in[5];
    float* out = (float*)d_out;
    (void)in_sizes; (void)n_in;

    cudaFuncSetAttribute(gemm_mma_kernel,
                         cudaFuncAttributeMaxDynamicSharedMemorySize, SMEM_BYTES);

    prep_kernel<<<(KN_COLS * G_PTS + 255) / 256, 256>>>(mesh, values, weights, grid, cell);
    interp_kernel<<<(P_ATOMS * G_PTS + 255) / 256, 256>>>(positions);

    cudaMemsetAsync(out, 0, (size_t)out_size * sizeof(float));

    dim3 ggrid(KN_PAD / BN, M_ROWS / BM, KSPLIT);   // (7, 16, 2) = 224 CTAs
    gemm_mma_kernel<<<ggrid, 256, SMEM_BYTES>>>(out);
}

// round 14
// speedup vs baseline: 1.2064x; 1.0303x over previous
#include <cuda_runtime.h>
#include <cuda_fp16.h>
#include <cstdint>

// ---------------------------------------------------------------------------
// Problem constants
// ---------------------------------------------------------------------------
#define P_ATOMS 512
#define A_CH    4
#define K_DIM   49
#define N_DIM   8
#define NM      128
#define NM2     (NM*NM)
#define NM3     (NM*NM*NM)
#define NB      64              // blocks per dim (Morton-2 mesh layout)
#define G_PTS   1900
#define G_PAD   1920
#define N_RAD   50
#define N_ANG   38
#define M_ROWS  (P_ATOMS*A_CH)  // 2048
#define KN_COLS (K_DIM*N_DIM)   // 392
#define KN_PAD  448             // 7 * 64

#define KSPLIT  2
#define KCHUNK  960             // 2*960 = 1920
#define BM      128
#define BN      64
#define BK      64
#define NIT     (KCHUNK/BK)     // 15
#define BKPH    (BK + 8)        // padded row stride in halves (72 -> 144 B rows)
#define NSTAGES 3

#define A_STAGE_H (BM * BKPH)           // 9216 halves (18432 B)
#define B_STAGE_H (BN * BKPH)           // 4608 halves (9216 B)
#define SMEM_BYTES (NSTAGES * (A_STAGE_H + B_STAGE_H) * 2)   // 82944 B

// ---------------------------------------------------------------------------
// Device scratch (zero-initialized at module load; pads never written)
// ---------------------------------------------------------------------------
__device__ __half g_Fh[M_ROWS * G_PAD];              // 7.9 MB
__device__ __half g_V2h[KN_PAD * G_PAD];             // 1.7 MB
__device__ __align__(128) uint2 g_meshT[NM3];        // 16.8 MB  fp16x4, Morton-2
__device__ float  g_w2[G_PTS];
__device__ float4 g_grid2[G_PTS];
__device__ float  g_inv[9];

// ---------------------------------------------------------------------------
// helpers
// ---------------------------------------------------------------------------
#define CP_ASYNC16(dst, src) \
    asm volatile("cp.async.cg.shared.global [%0], [%1], 16;" :: "r"(dst), "l"(src) : "memory")
#define CP_COMMIT() asm volatile("cp.async.commit_group;" ::: "memory")
#define CP_WAIT(n)  asm volatile("cp.async.wait_group %0;" :: "n"(n) : "memory")

#define MMA_F16(c, a, b) \
    asm volatile("mma.sync.aligned.m16n8k16.row.col.f32.f16.f16.f32 " \
        "{%0,%1,%2,%3}, {%4,%5,%6,%7}, {%8,%9}, {%0,%1,%2,%3};" \
        : "+f"((c)[0]), "+f"((c)[1]), "+f"((c)[2]), "+f"((c)[3]) \
        : "r"((a)[0]), "r"((a)[1]), "r"((a)[2]), "r"((a)[3]), \
          "r"((b)[0]), "r"((b)[1]))

#define LDSM_X4(r0, r1, r2, r3, addr) \
    asm volatile("ldmatrix.sync.aligned.m8n8.x4.shared.b16 {%0,%1,%2,%3}, [%4];" \
        : "=r"(r0), "=r"(r1), "=r"(r2), "=r"(r3) : "r"(addr))

__device__ __forceinline__ uint32_t pack_h2(float a, float b) {
    __half2 h = __floats2half2_rn(a, b);
    return *reinterpret_cast<uint32_t*>(&h);
}

// g2 = ang*50 + r   <->   g = r*38 + ang   (ray order — verified best)
__device__ __forceinline__ int g_from_g2(int g2) {
    int ang = g2 / N_RAD;
    int r   = g2 - ang * N_RAD;
    return r * N_ANG + ang;
}

// ---------------------------------------------------------------------------
// Kernel A: prep (Morton block transpose -> fp16, V2/weights/grid permute,
// cell inverse)
// ---------------------------------------------------------------------------
__global__ void __launch_bounds__(256)
prep_kernel(const float* __restrict__ mesh,
            const float* __restrict__ values,
            const float* __restrict__ weights,
            const float* __restrict__ grid,
            const float* __restrict__ cell) {
    int i = blockIdx.x * blockDim.x + threadIdx.x;
    if (i < NB*NB*NB) {
        int bz = i & 63, by = (i >> 6) & 63, bx = i >> 12;
        uint2 cells[8];
        #pragma unroll
        for (int jx = 0; jx < 2; ++jx) {
            #pragma unroll
            for (int jy = 0; jy < 2; ++jy) {
                int x = 2*bx + jx, y = 2*by + jy;
                const float* base = mesh + ((size_t)x * NM + y) * NM + 2*bz;
                float2 f0 = __ldg((const float2*)(base));
                float2 f1 = __ldg((const float2*)(base + NM3));
                float2 f2 = __ldg((const float2*)(base + 2*NM3));
                float2 f3 = __ldg((const float2*)(base + 3*NM3));
                int o = jx*4 + jy*2;
                cells[o    ] = make_uint2(pack_h2(f0.x, f1.x), pack_h2(f2.x, f3.x));
                cells[o + 1] = make_uint2(pack_h2(f0.y, f1.y), pack_h2(f2.y, f3.y));
            }
        }
        uint4* dst = reinterpret_cast<uint4*>(g_meshT + (size_t)i * 8);
        const uint4* src = reinterpret_cast<const uint4*>(cells);
        dst[0] = src[0]; dst[1] = src[1]; dst[2] = src[2]; dst[3] = src[3];
    }
    if (i < KN_COLS * G_PTS) {
        int row = i / G_PTS;
        int g2  = i - row * G_PTS;
        g_V2h[row * G_PAD + g2] = __float2half_rn(__ldg(values + row * G_PTS + g_from_g2(g2)));
    }
    if (i < G_PTS) {
        int g = g_from_g2(i);
        g_w2[i] = __ldg(weights + g);
        float4 gp;
        gp.x = __ldg(grid + g*3 + 0);
        gp.y = __ldg(grid + g*3 + 1);
        gp.z = __ldg(grid + g*3 + 2);
        gp.w = 0.f;
        g_grid2[i] = gp;
    }
    if (i == 0) {
        float c00 = cell[0], c01 = cell[1], c02 = cell[2];
        float c10 = cell[3], c11 = cell[4], c12 = cell[5];
        float c20 = cell[6], c21 = cell[7], c22 = cell[8];
        float m00 = c11*c22 - c12*c21;
        float m01 = c02*c21 - c01*c22;
        float m02 = c01*c12 - c02*c11;
        float m10 = c12*c20 - c10*c22;
        float m11 = c00*c22 - c02*c20;
        float m12 = c02*c10 - c00*c12;
        float m20 = c10*c21 - c11*c20;
        float m21 = c01*c20 - c00*c21;
        float m22 = c00*c11 - c01*c10;
        float rdet = 1.0f / (c00*m00 + c01*m10 + c02*m20);
        g_inv[0] = m00*rdet; g_inv[1] = m01*rdet; g_inv[2] = m02*rdet;
        g_inv[3] = m10*rdet; g_inv[4] = m11*rdet; g_inv[5] = m12*rdet;
        g_inv[6] = m20*rdet; g_inv[7] = m21*rdet; g_inv[8] = m22*rdet;
    }
}

// ---------------------------------------------------------------------------
// Kernel B: B-spline interpolation -> fp16 F[(p,a)][g2]
// 18 LDG.128 in two batches of 9 (one per z-block) to cut register pressure.
// ---------------------------------------------------------------------------
__global__ void __launch_bounds__(256)
interp_kernel(const float* __restrict__ pos) {
    int tid = blockIdx.x * blockDim.x + threadIdx.x;
    if (tid >= P_ATOMS * G_PTS) return;
    int p  = tid / G_PTS;
    int g2 = tid - p * G_PTS;

    float m00 = g_inv[0], m01 = g_inv[1], m02 = g_inv[2];
    float m10 = g_inv[3], m11 = g_inv[4], m12 = g_inv[5];
    float m20 = g_inv[6], m21 = g_inv[7], m22 = g_inv[8];

    float4 gp = g_grid2[g2];
    float px = __ldg(pos + p*3 + 0) + gp.x;
    float py = __ldg(pos + p*3 + 1) + gp.y;
    float pz = __ldg(pos + p*3 + 2) + gp.z;

    float fx = px*m00 + py*m10 + pz*m20;
    float fy = px*m01 + py*m11 + pz*m21;
    float fz = px*m02 + py*m12 + pz*m22;

    float wx[3], wy[3];
    int xpart[3], ypart[3];
    {
        float u = fx * (float)NM, nf = floorf(u + 0.5f), x = u - nf;
        wx[0] = 0.5f*(0.5f-x)*(0.5f-x); wx[1] = 0.75f - x*x; wx[2] = 0.5f*(0.5f+x)*(0.5f+x);
        int n = (int)nf;
        #pragma unroll
        for (int d = 0; d < 3; ++d) {
            int v = (n + d - 1 + 4*NM) & (NM-1);
            xpart[d] = (v >> 1) * 16384 + (v & 1) * 2;
        }
    }
    {
        float u = fy * (float)NM, nf = floorf(u + 0.5f), x = u - nf;
        wy[0] = 0.5f*(0.5f-x)*(0.5f-x); wy[1] = 0.75f - x*x; wy[2] = 0.5f*(0.5f+x)*(0.5f+x);
        int n = (int)nf;
        #pragma unroll
        for (int d = 0; d < 3; ++d) {
            int v = (n + d - 1 + 4*NM) & (NM-1);
            ypart[d] = (v >> 1) * 256 + (v & 1);
        }
    }
    int zpart[2];
    float zwA[2], zwB[2];
    {
        float u = fz * (float)NM, nf = floorf(u + 0.5f), x = u - nf;
        float wz0 = 0.5f*(0.5f-x)*(0.5f-x);
        float wz1 = 0.75f - x*x;
        float wz2 = 0.5f*(0.5f+x)*(0.5f+x);
        int nn = (int)nf + 4*NM;
        int b_lo = ((nn - 1) & (NM-1)) >> 1;
        int b_hi = ((nn + 1) & (NM-1)) >> 1;
        zpart[0] = b_lo * 4;
        zpart[1] = b_hi * 4;
        bool odd = (nn & 1) != 0;
        zwA[0] = odd ? wz0 : 0.f;
        zwB[0] = odd ? wz1 : wz0;
        zwA[1] = odd ? wz2 : wz1;
        zwB[1] = odd ? 0.f : wz2;
    }

    const uint4* mesh4 = reinterpret_cast<const uint4*>(g_meshT);

    float acc0 = 0.f, acc1 = 0.f, acc2 = 0.f, acc3 = 0.f;
    #pragma unroll
    for (int zb = 0; zb < 2; ++zb) {
        uint4 v9[9];
        #pragma unroll
        for (int dx = 0; dx < 3; ++dx)
            #pragma unroll
            for (int dy = 0; dy < 3; ++dy)
                v9[dx*3 + dy] = __ldg(mesh4 + xpart[dx] + ypart[dy] + zpart[zb]);

        float wA0 = zwA[zb], wB0 = zwB[zb];
        #pragma unroll
        for (int dx = 0; dx < 3; ++dx) {
            #pragma unroll
            for (int dy = 0; dy < 3; ++dy) {
                float wxy = wx[dx] * wy[dy];
                float wA = wxy * wA0;
                float wB = wxy * wB0;
                uint4 q = v9[dx*3 + dy];
                float2 a01 = __half22float2(*reinterpret_cast<__half2*>(&q.x));
                float2 a23 = __half22float2(*reinterpret_cast<__half2*>(&q.y));
                float2 b01 = __half22float2(*reinterpret_cast<__half2*>(&q.z));
                float2 b23 = __half22float2(*reinterpret_cast<__half2*>(&q.w));
                acc0 += wA * a01.x + wB * b01.x;
                acc1 += wA * a01.y + wB * b01.y;
                acc2 += wA * a23.x + wB * b23.x;
                acc3 += wA * a23.y + wB * b23.y;
            }
        }
    }

    float wt = g_w2[g2];
    g_Fh[(p*A_CH + 0)*G_PAD + g2] = __float2half_rn(acc0 * wt);
    g_Fh[(p*A_CH + 1)*G_PAD + g2] = __float2half_rn(acc1 * wt);
    g_Fh[(p*A_CH + 2)*G_PAD + g2] = __float2half_rn(acc2 * wt);
    g_Fh[(p*A_CH + 3)*G_PAD + g2] = __float2half_rn(acc3 * wt);
}

// ---------------------------------------------------------------------------
// Kernel C: fp16 mma.sync GEMM, BK=64 (half the barriers), 3-stage cp.async,
// split-K 2. Block 128x64, 8 warps (warp tile 32x32), 2 CTAs/SM (83 KB smem).
// ---------------------------------------------------------------------------
__global__ void __launch_bounds__(256, 2)
gemm_mma_kernel(float* __restrict__ out) {
    extern __shared__ __half smemh[];
    __half* As = smemh;                          // [3][BM][BKPH]
    __half* Bs = smemh + NSTAGES * A_STAGE_H;    // [3][BN][BKPH]

    const int tid  = threadIdx.x;
    const int lane = tid & 31;
    const int wid  = tid >> 5;
    const int warpM = wid & 3;    // 4 warps over M (32 rows each)
    const int warpN = wid >> 2;   // 2 warps over N (32 cols each)
    const int gRow = lane >> 2;
    const int gCol = lane & 3;

    const int n0    = blockIdx.x * BN;
    const int m0    = blockIdx.y * BM;
    const int bz    = blockIdx.z;
    const int kbase = bz * KCHUNK;

    uint32_t asBase = (uint32_t)__cvta_generic_to_shared(As);
    uint32_t bsBase = (uint32_t)__cvta_generic_to_shared(Bs);

    const int rowA_l = (lane & 7) + (((lane >> 3) & 1) << 3);
    const int kA_l   = (lane >> 4) << 3;
    const int rowB_l = (lane & 7) + ((lane >> 4) << 3);
    const int kB_l   = ((lane >> 3) & 1) << 3;

    // one stage: A = 1024 cp16 (4/thread), B = 512 cp16 (2/thread)
    auto load_stage = [&](int it, int buf) {
        int kofs = kbase + it * BK;
        #pragma unroll
        for (int i = 0; i < 4; ++i) {
            int e   = tid + i * 256;
            int row = e >> 3;          // 0..127
            int c8  = e & 7;           // 8 chunks of 16B per 64-half row
            uint32_t dstA = asBase + (buf * A_STAGE_H + row * BKPH) * 2 + c8 * 16;
            const __half* srcA = g_Fh + (size_t)(m0 + row) * G_PAD + kofs + c8 * 8;
            CP_ASYNC16(dstA, srcA);
        }
        #pragma unroll
        for (int i = 0; i < 2; ++i) {
            int e   = tid + i * 256;
            int row = e >> 3;          // 0..63
            int c8  = e & 7;
            uint32_t dstB = bsBase + (buf * B_STAGE_H + row * BKPH) * 2 + c8 * 16;
            const __half* srcB = g_V2h + (size_t)(n0 + row) * G_PAD + kofs + c8 * 8;
            CP_ASYNC16(dstB, srcB);
        }
        CP_COMMIT();
    };

    float c[2][4][4];
    #pragma unroll
    for (int mt = 0; mt < 2; ++mt)
        #pragma unroll
        for (int nt = 0; nt < 4; ++nt)
            #pragma unroll
            for (int j = 0; j < 4; ++j) c[mt][nt][j] = 0.f;

    load_stage(0, 0);
    load_stage(1, 1);

    #pragma unroll 1
    for (int it = 0; it < NIT; ++it) {
        int buf = it % NSTAGES;
        if (it < NIT - 1) { CP_WAIT(1); } else { CP_WAIT(0); }
        __syncthreads();
        if (it + 2 < NIT) load_stage(it + 2, (it + 2) % NSTAGES);

        uint32_t aBufBase = asBase + (buf * A_STAGE_H) * 2;
        uint32_t bBufBase = bsBase + (buf * B_STAGE_H) * 2;

        #pragma unroll
        for (int ks = 0; ks < 4; ++ks) {
            uint32_t a[2][4], b[4][2];
            #pragma unroll
            for (int mt = 0; mt < 2; ++mt) {
                int r = warpM * 32 + mt * 16 + rowA_l;
                uint32_t addr = aBufBase + (r * BKPH + ks * 16 + kA_l) * 2;
                LDSM_X4(a[mt][0], a[mt][1], a[mt][2], a[mt][3], addr);
            }
            #pragma unroll
            for (int pr = 0; pr < 2; ++pr) {
                int rb = warpN * 32 + pr * 16 + rowB_l;
                uint32_t addr = bBufBase + (rb * BKPH + ks * 16 + kB_l) * 2;
                LDSM_X4(b[2*pr][0], b[2*pr][1], b[2*pr+1][0], b[2*pr+1][1], addr);
            }
            #pragma unroll
            for (int mt = 0; mt < 2; ++mt)
                #pragma unroll
                for (int nt = 0; nt < 4; ++nt)
                    MMA_F16(c[mt][nt], a[mt], b[nt]);
        }
    }

    // epilogue: atomicAdd into out, pkan layout
    #pragma unroll
    for (int mt = 0; mt < 2; ++mt) {
        int row0 = m0 + warpM * 32 + mt * 16 + gRow;
        #pragma unroll
        for (int nt = 0; nt < 4; ++nt) {
            int col = n0 + warpN * 32 + nt * 8 + gCol * 2;
            if (col < KN_COLS) {
                int k = col >> 3;
                int n = col & 7;
                {
                    int p = row0 >> 2, a = row0 & 3;
                    float* dst = out + ((p * K_DIM + k) * A_CH + a) * N_DIM + n;
                    atomicAdd(dst,     c[mt][nt][0]);
                    atomicAdd(dst + 1, c[mt][nt][1]);
                }
                {
                    int row1 = row0 + 8;
                    int p = row1 >> 2, a = row1 & 3;
                    float* dst = out + ((p * K_DIM + k) * A_CH + a) * N_DIM + n;
                    atomicAdd(dst,     c[mt][nt][2]);
                    atomicAdd(dst + 1, c[mt][nt][3]);
                }
            }
        }
    }
}

// ---------------------------------------------------------------------------
extern "C" void kernel_launch(void* const* d_in, const int* in_sizes, int n_in,
                              void* d_out, int out_size) {
    const float* positions = (const float*)d_in[0];
    const float* mesh      = (const float*)d_in[1];
    const float* cell      = (const float*)d_in[2];
    const float* values    = (const float*)d_in[3];
    const float* weights   = (const float*)d_in[4];
    const float* grid      = (const float*)d_in[5];
    float* out = (float*)d_out;
    (void)in_sizes; (void)n_in;

    cudaFuncSetAttribute(gemm_mma_kernel,
                         cudaFuncAttributeMaxDynamicSharedMemorySize, SMEM_BYTES);

    prep_kernel<<<(KN_COLS * G_PTS + 255) / 256, 256>>>(mesh, values, weights, grid, cell);
    interp_kernel<<<(P_ATOMS * G_PTS + 255) / 256, 256>>>(positions);

    cudaMemsetAsync(out, 0, (size_t)out_size * sizeof(float));

    dim3 ggrid(KN_PAD / BN, M_ROWS / BM, KSPLIT);   // (7, 16, 2) = 224 CTAs
    gemm_mma_kernel<<<ggrid, 256, SMEM_BYTES>>>(out);
}